// round 7
// baseline (speedup 1.0000x reference)
#include <cuda_runtime.h>
#include <math.h>

// Problem shapes (fixed by the dataset)
#define B_    16
#define C_    192
#define H_    48
#define W_    48
#define IMG_  768
#define HW_   (H_*W_)                 // 2304
#define HW2_  (HW_/2)                 // 1152 float2 per (b,c,param) plane
#define NY_   (B_*C_*HW_)             // 7,077,888
#define NY2_  (NY_/2)                 // 3,538,944 float2 y elements
#define NX4_  (B_*3*IMG_*IMG_/4)      // 7,077,888 float4 pairs for MSE
#define NZ_   (B_*C_*12*12)           // 442,368
#define NZ4_  (NZ_/4)

#define NBLK 1184                      // 8 * 148 SMs
#define NTHR 256

__device__ double g_sum[3];            // [0]=sum sq err, [1]=sum ln_pmf_y, [2]=sum ln_pmf_z
__device__ unsigned int g_done;

__global__ void rd_zero_kernel() {
    if (threadIdx.x < 3) g_sum[threadIdx.x] = 0.0;
    if (threadIdx.x == 0) g_done = 0u;
}

__device__ __forceinline__ float warp_sum(float v) {
    #pragma unroll
    for (int o = 16; o > 0; o >>= 1) v += __shfl_down_sync(0xffffffffu, v, o);
    return v;
}

// Standard normal CDF via Abramowitz-Stegun 7.1.26 erfc (abs err ~1.5e-7).
__device__ __forceinline__ float ncdf(float t) {
    float a  = t * 0.70710678118654752f;
    float x  = fabsf(a);
    float tt = __fdividef(1.0f, fmaf(0.3275911f, x, 1.0f));
    float poly = tt * fmaf(tt, fmaf(tt, fmaf(tt, fmaf(tt, 1.061405429f, -1.453152027f),
                                             1.421413741f), -0.284496736f), 0.254829592f);
    float half_tail = 0.5f * poly * __expf(-x * x);   // = 0.5*erfc(x)
    return (a >= 0.0f) ? (1.0f - half_tail) : half_tail;
}

// ln of GMM pmf for one element. Logits are N(0,1) -> exp() is safe unshifted.
__device__ __forceinline__ float gmm_ln_pmf(float w0, float w1, float w2,
                                            float m0, float m1, float m2,
                                            float ls0, float ls1, float ls2,
                                            float yv) {
    float i0 = fminf(__expf(-ls0), 1e5f);
    float i1 = fminf(__expf(-ls1), 1e5f);
    float i2 = fminf(__expf(-ls2), 1e5f);

    float yp = yv + 0.5f, ym = yv - 0.5f;
    float p0 = fmaxf(ncdf((yp - m0) * i0) - ncdf((ym - m0) * i0), 1e-6f);
    float p1 = fmaxf(ncdf((yp - m1) * i1) - ncdf((ym - m1) * i1), 1e-6f);
    float p2 = fmaxf(ncdf((yp - m2) * i2) - ncdf((ym - m2) * i2), 1e-6f);

    float e0 = __expf(w0), e1 = __expf(w1), e2 = __expf(w2);
    float num = fmaf(e2, p2, fmaf(e1, p1, e0 * p0));
    float den = e0 + e1 + e2;
    return __logf(num) - __logf(den);
}

// One GMM iteration's operand bundle (10 float2 streaming loads).
struct GBundle {
    float2 w0, w1, w2, m0, m1, m2, s0, s1, s2, yv;
};

__device__ __forceinline__ GBundle load_gbundle(const float* __restrict__ params,
                                                const float* __restrict__ y, int i) {
    int hw2 = i % HW2_;
    int bc  = i / HW2_;
    const float2* p = (const float2*)(params + (size_t)bc * 9 * HW_) + hw2;
    GBundle g;
    g.w0 = __ldcs(&p[0*HW2_]); g.w1 = __ldcs(&p[1*HW2_]); g.w2 = __ldcs(&p[2*HW2_]);
    g.m0 = __ldcs(&p[3*HW2_]); g.m1 = __ldcs(&p[4*HW2_]); g.m2 = __ldcs(&p[5*HW2_]);
    g.s0 = __ldcs(&p[6*HW2_]); g.s1 = __ldcs(&p[7*HW2_]); g.s2 = __ldcs(&p[8*HW2_]);
    g.yv = __ldcs(((const float2*)y) + i);
    return g;
}

__global__ void __launch_bounds__(NTHR)
rd_main_kernel(const float* __restrict__ x,
               const float* __restrict__ xhat,
               const float* __restrict__ params,
               const float* __restrict__ y,
               const float* __restrict__ z,
               float* __restrict__ out, int out_size)
{
    const int tid    = blockIdx.x * NTHR + threadIdx.x;
    const int stride = gridDim.x * NTHR;

    float mse_acc = 0.f;
    float ry_acc  = 0.f;

    // Warp-parity phase alternation: every SM hosts both streaming (MSE) and
    // compute (GMM) warps concurrently.
    const int order = (tid >> 5) & 1;

    for (int pass = 0; pass < 2; ++pass) {
        if ((pass ^ order) == 0) {
            // ---------------- MSE over images (float4, 4x unroll) ----------
            const float4* a4 = (const float4*)x;
            const float4* b4 = (const float4*)xhat;
            int i = tid;
            for (; i + 3 * stride < NX4_; i += 4 * stride) {
                float4 a0 = __ldcs(a4 + i),            b0 = __ldcs(b4 + i);
                float4 a1 = __ldcs(a4 + i + stride),   b1 = __ldcs(b4 + i + stride);
                float4 a2 = __ldcs(a4 + i + 2*stride), b2 = __ldcs(b4 + i + 2*stride);
                float4 a3 = __ldcs(a4 + i + 3*stride), b3 = __ldcs(b4 + i + 3*stride);
                float d0 = b0.x-a0.x, d1 = b0.y-a0.y, d2 = b0.z-a0.z, d3 = b0.w-a0.w;
                mse_acc += d0*d0 + d1*d1 + d2*d2 + d3*d3;
                d0 = b1.x-a1.x; d1 = b1.y-a1.y; d2 = b1.z-a1.z; d3 = b1.w-a1.w;
                mse_acc += d0*d0 + d1*d1 + d2*d2 + d3*d3;
                d0 = b2.x-a2.x; d1 = b2.y-a2.y; d2 = b2.z-a2.z; d3 = b2.w-a2.w;
                mse_acc += d0*d0 + d1*d1 + d2*d2 + d3*d3;
                d0 = b3.x-a3.x; d1 = b3.y-a3.y; d2 = b3.z-a3.z; d3 = b3.w-a3.w;
                mse_acc += d0*d0 + d1*d1 + d2*d2 + d3*d3;
            }
            for (; i < NX4_; i += stride) {
                float4 a = __ldcs(a4 + i), b = __ldcs(b4 + i);
                float d0 = b.x-a.x, d1 = b.y-a.y, d2 = b.z-a.z, d3 = b.w-a.w;
                mse_acc += d0*d0 + d1*d1 + d2*d2 + d3*d3;
            }
        } else {
            // -------- GMM latent rate, software-pipelined (double buffer) ---
            // Next iteration's 10 loads are issued BEFORE current math, so the
            // warp keeps ~640B outstanding through its whole compute tail.
            int i = tid;
            if (i < NY2_) {
                GBundle cur = load_gbundle(params, y, i);
                for (; i < NY2_; ) {
                    int inext = i + stride;
                    int ipf   = (inext < NY2_) ? inext : i;   // clamp: redundant safe load
                    GBundle nxt = load_gbundle(params, y, ipf);

                    ry_acc += gmm_ln_pmf(cur.w0.x, cur.w1.x, cur.w2.x,
                                         cur.m0.x, cur.m1.x, cur.m2.x,
                                         cur.s0.x, cur.s1.x, cur.s2.x, cur.yv.x);
                    ry_acc += gmm_ln_pmf(cur.w0.y, cur.w1.y, cur.w2.y,
                                         cur.m0.y, cur.m1.y, cur.m2.y,
                                         cur.s0.y, cur.s1.y, cur.s2.y, cur.yv.y);
                    cur = nxt;
                    i = inext;
                }
            }
        }
    }

    // ---------------- hyperlatent rate (float4) -----------------------------
    float rz_acc = 0.f;
    {
        const float4* z4 = (const float4*)z;
        for (int i = tid; i < NZ4_; i += stride) {
            float4 zv = __ldcs(z4 + i);
            rz_acc += __logf(fmaxf(ncdf(zv.x + 0.5f) - ncdf(zv.x - 0.5f), 1e-6f));
            rz_acc += __logf(fmaxf(ncdf(zv.y + 0.5f) - ncdf(zv.y - 0.5f), 1e-6f));
            rz_acc += __logf(fmaxf(ncdf(zv.z + 0.5f) - ncdf(zv.z - 0.5f), 1e-6f));
            rz_acc += __logf(fmaxf(ncdf(zv.w + 0.5f) - ncdf(zv.w - 0.5f), 1e-6f));
        }
    }

    // ---------------- block reduce + global accumulate ----------------------
    __shared__ float sm[3][NTHR / 32];
    int lane = threadIdx.x & 31;
    int wid  = threadIdx.x >> 5;

    float v0 = warp_sum(mse_acc);
    float v1 = warp_sum(ry_acc);
    float v2 = warp_sum(rz_acc);
    if (lane == 0) { sm[0][wid] = v0; sm[1][wid] = v1; sm[2][wid] = v2; }
    __syncthreads();

    if (wid == 0) {
        float a0 = (lane < NTHR/32) ? sm[0][lane] : 0.f;
        float a1 = (lane < NTHR/32) ? sm[1][lane] : 0.f;
        float a2 = (lane < NTHR/32) ? sm[2][lane] : 0.f;
        a0 = warp_sum(a0); a1 = warp_sum(a1); a2 = warp_sum(a2);
        if (lane == 0) {
            atomicAdd(&g_sum[0], (double)a0);
            atomicAdd(&g_sum[1], (double)a1);
            atomicAdd(&g_sum[2], (double)a2);
        }
    }

    // ---------------- last-block finalize ------------------------------------
    __shared__ int is_last;
    if (threadIdx.x == 0) {
        __threadfence();
        unsigned v = atomicAdd(&g_done, 1u);
        is_last = (v == gridDim.x - 1u) ? 1 : 0;
    }
    __syncthreads();

    if (is_last && threadIdx.x == 0) {
        __threadfence();
        double s_mse = ((volatile double*)g_sum)[0];
        double s_ly  = ((volatile double*)g_sum)[1];
        double s_lz  = ((volatile double*)g_sum)[2];

        const double ln2 = 0.69314718055994530942;
        double distortion = s_mse / ((double)B_ * 3.0 * IMG_ * IMG_);
        double rate_y = -s_ly / ln2;
        double rate_z = -s_lz / ln2;
        double rate_mean = (rate_y + rate_z) / (double)B_;
        double num_pixels = (double)B_ * IMG_ * IMG_;
        double bpp = rate_mean / num_pixels;
        double loss = 0.01 * 255.0 * 255.0 * distortion + bpp;

        out[0] = (float)loss;
        if (out_size >= 3) {
            out[1] = (float)distortion;
            out[2] = (float)bpp;
        }
    }
}

extern "C" void kernel_launch(void* const* d_in, const int* in_sizes, int n_in,
                              void* d_out, int out_size) {
    const float* x      = (const float*)d_in[0];
    const float* xhat   = (const float*)d_in[1];
    const float* params = (const float*)d_in[2];
    const float* y      = (const float*)d_in[3];
    const float* z      = (const float*)d_in[4];
    float* out = (float*)d_out;

    rd_zero_kernel<<<1, 32>>>();
    rd_main_kernel<<<NBLK, NTHR>>>(x, xhat, params, y, z, out, out_size);
}

// round 8
// speedup vs baseline: 1.2391x; 1.2391x over previous
#include <cuda_runtime.h>
#include <math.h>

// Problem shapes (fixed by the dataset)
#define B_    16
#define C_    192
#define H_    48
#define W_    48
#define IMG_  768
#define HW_   (H_*W_)                 // 2304
#define HW4_  (HW_/4)                 // 576 float4 per (b,c,param) plane
#define NY_   (B_*C_*HW_)             // 7,077,888
#define NY4_  (NY_/4)                 // 1,769,472 float4 y elements
#define NX4_  (B_*3*IMG_*IMG_/4)      // 7,077,888 float4 pairs for MSE
#define NZ_   (B_*C_*12*12)           // 442,368
#define NZ4_  (NZ_/4)

#define NBLK 1184                      // 8 * 148 SMs
#define NTHR 256

// Accumulators. Zero-initialized at module load; the finalizing block re-zeros
// them after reading, so every (graph-replayed) launch starts from zeros
// without a separate zeroing kernel.
__device__ double g_sum[3];            // [0]=sum sq err, [1]=sum ln_pmf_y, [2]=sum ln_pmf_z
__device__ unsigned int g_done;

__device__ __forceinline__ float warp_sum(float v) {
    #pragma unroll
    for (int o = 16; o > 0; o >>= 1) v += __shfl_down_sync(0xffffffffu, v, o);
    return v;
}

// Standard normal CDF via Abramowitz-Stegun 7.1.26 erfc (abs err ~1.5e-7).
__device__ __forceinline__ float ncdf(float t) {
    float a  = t * 0.70710678118654752f;
    float x  = fabsf(a);
    float tt = __fdividef(1.0f, fmaf(0.3275911f, x, 1.0f));
    float poly = tt * fmaf(tt, fmaf(tt, fmaf(tt, fmaf(tt, 1.061405429f, -1.453152027f),
                                             1.421413741f), -0.284496736f), 0.254829592f);
    float half_tail = 0.5f * poly * __expf(-x * x);   // = 0.5*erfc(x)
    return (a >= 0.0f) ? (1.0f - half_tail) : half_tail;
}

// ln of GMM pmf for one element. Logits are N(0,1) -> exp() is safe unshifted.
__device__ __forceinline__ float gmm_ln_pmf(float w0, float w1, float w2,
                                            float m0, float m1, float m2,
                                            float ls0, float ls1, float ls2,
                                            float yv) {
    // 1/scale with scale = clip(exp(ls), 1e-5) -> inv = min(exp(-ls), 1e5)
    float i0 = fminf(__expf(-ls0), 1e5f);
    float i1 = fminf(__expf(-ls1), 1e5f);
    float i2 = fminf(__expf(-ls2), 1e5f);

    float yp = yv + 0.5f, ym = yv - 0.5f;
    float p0 = fmaxf(ncdf((yp - m0) * i0) - ncdf((ym - m0) * i0), 1e-6f);
    float p1 = fmaxf(ncdf((yp - m1) * i1) - ncdf((ym - m1) * i1), 1e-6f);
    float p2 = fmaxf(ncdf((yp - m2) * i2) - ncdf((ym - m2) * i2), 1e-6f);

    float e0 = __expf(w0), e1 = __expf(w1), e2 = __expf(w2);
    float num = fmaf(e2, p2, fmaf(e1, p1, e0 * p0));
    float den = e0 + e1 + e2;
    return __logf(num) - __logf(den);
}

__global__ void __launch_bounds__(NTHR)
rd_main_kernel(const float* __restrict__ x,
               const float* __restrict__ xhat,
               const float* __restrict__ params,
               const float* __restrict__ y,
               const float* __restrict__ z,
               float* __restrict__ out, int out_size)
{
    const int tid    = blockIdx.x * NTHR + threadIdx.x;
    const int stride = gridDim.x * NTHR;

    float mse_acc = 0.f;
    float ry_acc  = 0.f;

    // Block-parity phase alternation (R4 schedule: best measured).
    const int order = blockIdx.x & 1;

    for (int pass = 0; pass < 2; ++pass) {
        if ((pass ^ order) == 0) {
            // ---------------- MSE over images (float4, 4x unroll, evict-first)
            const float4* a4 = (const float4*)x;
            const float4* b4 = (const float4*)xhat;
            int i = tid;
            for (; i + 3 * stride < NX4_; i += 4 * stride) {
                float4 a0 = __ldcs(a4 + i),            b0 = __ldcs(b4 + i);
                float4 a1 = __ldcs(a4 + i + stride),   b1 = __ldcs(b4 + i + stride);
                float4 a2 = __ldcs(a4 + i + 2*stride), b2 = __ldcs(b4 + i + 2*stride);
                float4 a3 = __ldcs(a4 + i + 3*stride), b3 = __ldcs(b4 + i + 3*stride);
                float d0 = b0.x-a0.x, d1 = b0.y-a0.y, d2 = b0.z-a0.z, d3 = b0.w-a0.w;
                mse_acc += d0*d0 + d1*d1 + d2*d2 + d3*d3;
                d0 = b1.x-a1.x; d1 = b1.y-a1.y; d2 = b1.z-a1.z; d3 = b1.w-a1.w;
                mse_acc += d0*d0 + d1*d1 + d2*d2 + d3*d3;
                d0 = b2.x-a2.x; d1 = b2.y-a2.y; d2 = b2.z-a2.z; d3 = b2.w-a2.w;
                mse_acc += d0*d0 + d1*d1 + d2*d2 + d3*d3;
                d0 = b3.x-a3.x; d1 = b3.y-a3.y; d2 = b3.z-a3.z; d3 = b3.w-a3.w;
                mse_acc += d0*d0 + d1*d1 + d2*d2 + d3*d3;
            }
            for (; i < NX4_; i += stride) {
                float4 a = __ldcs(a4 + i), b = __ldcs(b4 + i);
                float d0 = b.x-a.x, d1 = b.y-a.y, d2 = b.z-a.z, d3 = b.w-a.w;
                mse_acc += d0*d0 + d1*d1 + d2*d2 + d3*d3;
            }
        } else {
            // ---------------- GMM latent rate (float4 vectorized) ----------
            for (int i = tid; i < NY4_; i += stride) {
                int hw4 = i % HW4_;
                int bc  = i / HW4_;
                const float4* p = (const float4*)(params + (size_t)bc * 9 * HW_) + hw4;

                float4 W0 = p[0*HW4_], W1 = p[1*HW4_], W2 = p[2*HW4_];
                float4 M0 = p[3*HW4_], M1 = p[4*HW4_], M2 = p[5*HW4_];
                float4 S0 = p[6*HW4_], S1 = p[7*HW4_], S2 = p[8*HW4_];
                float4 Yv = ((const float4*)y)[i];

                ry_acc += gmm_ln_pmf(W0.x, W1.x, W2.x, M0.x, M1.x, M2.x,
                                     S0.x, S1.x, S2.x, Yv.x);
                ry_acc += gmm_ln_pmf(W0.y, W1.y, W2.y, M0.y, M1.y, M2.y,
                                     S0.y, S1.y, S2.y, Yv.y);
                ry_acc += gmm_ln_pmf(W0.z, W1.z, W2.z, M0.z, M1.z, M2.z,
                                     S0.z, S1.z, S2.z, Yv.z);
                ry_acc += gmm_ln_pmf(W0.w, W1.w, W2.w, M0.w, M1.w, M2.w,
                                     S0.w, S1.w, S2.w, Yv.w);
            }
        }
    }

    // ---------------- hyperlatent rate (float4, evict-first) ----------------
    float rz_acc = 0.f;
    {
        const float4* z4 = (const float4*)z;
        for (int i = tid; i < NZ4_; i += stride) {
            float4 zv = __ldcs(z4 + i);
            rz_acc += __logf(fmaxf(ncdf(zv.x + 0.5f) - ncdf(zv.x - 0.5f), 1e-6f));
            rz_acc += __logf(fmaxf(ncdf(zv.y + 0.5f) - ncdf(zv.y - 0.5f), 1e-6f));
            rz_acc += __logf(fmaxf(ncdf(zv.z + 0.5f) - ncdf(zv.z - 0.5f), 1e-6f));
            rz_acc += __logf(fmaxf(ncdf(zv.w + 0.5f) - ncdf(zv.w - 0.5f), 1e-6f));
        }
    }

    // ---------------- block reduce + global accumulate ----------------------
    __shared__ float sm[3][NTHR / 32];
    int lane = threadIdx.x & 31;
    int wid  = threadIdx.x >> 5;

    float v0 = warp_sum(mse_acc);
    float v1 = warp_sum(ry_acc);
    float v2 = warp_sum(rz_acc);
    if (lane == 0) { sm[0][wid] = v0; sm[1][wid] = v1; sm[2][wid] = v2; }
    __syncthreads();

    if (wid == 0) {
        float a0 = (lane < NTHR/32) ? sm[0][lane] : 0.f;
        float a1 = (lane < NTHR/32) ? sm[1][lane] : 0.f;
        float a2 = (lane < NTHR/32) ? sm[2][lane] : 0.f;
        a0 = warp_sum(a0); a1 = warp_sum(a1); a2 = warp_sum(a2);
        if (lane == 0) {
            atomicAdd(&g_sum[0], (double)a0);
            atomicAdd(&g_sum[1], (double)a1);
            atomicAdd(&g_sum[2], (double)a2);
        }
    }

    // ---------------- last-block finalize + self-reset -----------------------
    __shared__ int is_last;
    if (threadIdx.x == 0) {
        __threadfence();
        unsigned v = atomicAdd(&g_done, 1u);
        is_last = (v == gridDim.x - 1u) ? 1 : 0;
    }
    __syncthreads();

    if (is_last && threadIdx.x == 0) {
        __threadfence();
        double s_mse = ((volatile double*)g_sum)[0];
        double s_ly  = ((volatile double*)g_sum)[1];
        double s_lz  = ((volatile double*)g_sum)[2];

        const double ln2 = 0.69314718055994530942;
        double distortion = s_mse / ((double)B_ * 3.0 * IMG_ * IMG_);
        double rate_y = -s_ly / ln2;
        double rate_z = -s_lz / ln2;
        double rate_mean = (rate_y + rate_z) / (double)B_;
        double num_pixels = (double)B_ * IMG_ * IMG_;
        double bpp = rate_mean / num_pixels;
        double loss = 0.01 * 255.0 * 255.0 * distortion + bpp;

        out[0] = (float)loss;
        if (out_size >= 3) {
            out[1] = (float)distortion;
            out[2] = (float)bpp;
        }

        // Reset accumulators for the next launch (graph replay). Globals are
        // zero at module load, so state is identical before every launch.
        ((volatile double*)g_sum)[0] = 0.0;
        ((volatile double*)g_sum)[1] = 0.0;
        ((volatile double*)g_sum)[2] = 0.0;
        __threadfence();
        g_done = 0u;
    }
}

extern "C" void kernel_launch(void* const* d_in, const int* in_sizes, int n_in,
                              void* d_out, int out_size) {
    const float* x      = (const float*)d_in[0];
    const float* xhat   = (const float*)d_in[1];
    const float* params = (const float*)d_in[2];
    const float* y      = (const float*)d_in[3];
    const float* z      = (const float*)d_in[4];
    float* out = (float*)d_out;

    rd_main_kernel<<<NBLK, NTHR>>>(x, xhat, params, y, z, out, out_size);
}